// round 11
// baseline (speedup 1.0000x reference)
#include <cuda_runtime.h>
#include <math.h>
#include <stdint.h>

// Problem constants
#define Lq     512
#define Bsz    4
#define Hn     16
#define LL     (512*512)

// ---------------- scratch (single static device buffer; no allocs) ----------
#define OFF_H    0u
#define OFF_QKV  (OFF_H    + 2048u*512u)          // 2048x1536
#define OFF_PEP  (OFF_QKV  + 2048u*1536u)         // 32x1536
#define OFF_EEP  (OFF_PEP  + 32u*1536u)           // 16x1536
#define OFF_APE  (OFF_EEP  + 16u*1536u)           // 32*4*16*512
#define OFF_AEE  (OFF_APE  + 32u*4u*16u*512u)
#define OFF_BPE  (OFF_AEE  + 16u*4u*16u*512u)
#define OFF_BEE  (OFF_BPE  + 32u*4u*16u*512u)
#define OFF_AO   (OFF_BEE  + 16u*4u*16u*512u)     // 2048x512
#define OFF_X1   (OFF_AO   + 2048u*512u)
#define OFF_H2   (OFF_X1   + 2048u*512u)
#define OFF_FF   (OFF_H2   + 2048u*512u)          // 2048x2048
#define OFF_MP   (OFF_FF   + 2048u*2048u)         // 64*512*8 row-max partials
#define SCRATCH_FLOATS (OFF_MP + 64u*512u*8u)

__device__ float g_scratch[SCRATCH_FLOATS];

// ---------------- helpers ----------------------------------------------------
__device__ __forceinline__ float fast_exp(float x) {
    float t = x * 1.4426950408889634f;
    t = fmaxf(t, -100.f);
    float r = rintf(t);
    float f = t - r;
    float p =            1.3333558146e-3f;
    p = fmaf(p, f, 9.6181291076e-3f);
    p = fmaf(p, f, 5.5504108664e-2f);
    p = fmaf(p, f, 2.4022650696e-1f);
    p = fmaf(p, f, 6.9314718056e-1f);
    p = fmaf(p, f, 1.0f);
    int e = (int)r;
    float sc = __int_as_float((e + 127) << 23);
    return p * sc;
}

__device__ __forceinline__ uint32_t f2tf32(float x) {
    uint32_t r;
    asm("cvt.rna.tf32.f32 %0, %1;" : "=r"(r) : "f"(x));
    return r;
}

// split x into (hi, lo) tf32 pair
__device__ __forceinline__ uint2 tf32_split(float x) {
    uint2 s;
    s.x = f2tf32(x);
    s.y = f2tf32(x - __uint_as_float(s.x));
    return s;
}

__device__ __forceinline__ void mma_tf32(float* c, const uint32_t* a, const uint32_t* b) {
    asm volatile(
        "mma.sync.aligned.m16n8k8.row.col.f32.tf32.tf32.f32 "
        "{%0,%1,%2,%3}, {%4,%5,%6,%7}, {%8,%9}, {%0,%1,%2,%3};"
        : "+f"(c[0]), "+f"(c[1]), "+f"(c[2]), "+f"(c[3])
        : "r"(a[0]), "r"(a[1]), "r"(a[2]), "r"(a[3]), "r"(b[0]), "r"(b[1]));
}

// ---------------- LayerNorm ---------------------------------------------------
__global__ void ln_kernel(const float* __restrict__ in, float* __restrict__ out,
                          const float* __restrict__ gamma, const float* __restrict__ beta) {
    int row = blockIdx.x;
    const float* xr = in + (size_t)row * 512;
    int t = threadIdx.x;
    float v[4];
    float s = 0.f;
#pragma unroll
    for (int i = 0; i < 4; i++) { v[i] = xr[t + i * 128]; s += v[i]; }
    __shared__ float red[4];
#pragma unroll
    for (int o = 16; o; o >>= 1) s += __shfl_xor_sync(0xffffffffu, s, o);
    if ((t & 31) == 0) red[t >> 5] = s;
    __syncthreads();
    float mean = (red[0] + red[1] + red[2] + red[3]) * (1.f / 512.f);
    float vs = 0.f;
#pragma unroll
    for (int i = 0; i < 4; i++) { float d = v[i] - mean; vs += d * d; }
#pragma unroll
    for (int o = 16; o; o >>= 1) vs += __shfl_xor_sync(0xffffffffu, vs, o);
    __syncthreads();
    if ((t & 31) == 0) red[t >> 5] = vs;
    __syncthreads();
    float var = (red[0] + red[1] + red[2] + red[3]) * (1.f / 512.f);
    float rstd = rsqrtf(var + 1e-5f);
    float* orow = out + (size_t)row * 512;
#pragma unroll
    for (int i = 0; i < 4; i++) {
        int c = t + i * 128;
        orow[c] = (v[i] - mean) * rstd * gamma[c] + beta[c];
    }
}

// ---------------- tf32 split MMA GEMM, pre-split smem -------------------------
// C[M,N] = A[M,K] @ B[K,N] + bias  (+res | gelu). Tile 128 x TN, k-chunk 8.
// smem holds (hi,lo) tf32 pairs; consumers do zero cvt, one LDS.64 per frag reg.
// 256 threads = 8 warps, 2(M) x 4(N). M,K mult of 128/8; N mult of TN.
template<int TN>
__global__ __launch_bounds__(256)
void mma_gemm_kernel(const float* __restrict__ A, const float* __restrict__ Bm,
                     const float* __restrict__ bias, const float* __restrict__ res,
                     float* __restrict__ C, int M, int N, int K, int epi) {
    constexpr int NT = TN / 32;          // n-tiles per warp (4 or 2)
    constexpr int ASTR = 132;            // A smem row stride (words of uint2)
    constexpr int BSTR = TN + 4;         // B smem row stride
    __shared__ uint2 As2[2][8][ASTR];    // [k][row] (hi,lo)
    __shared__ uint2 Bs2[2][8][BSTR];    // [k][col]

    int tid = threadIdx.x;
    int lane = tid & 31, wid = tid >> 5;
    int warp_m = wid >> 2, warp_n = wid & 3;
    int g = lane >> 2, q = lane & 3;
    int bm = blockIdx.y * 128, bn = blockIdx.x * TN;

    float c[4][NT][4];
#pragma unroll
    for (int mt = 0; mt < 4; mt++)
#pragma unroll
        for (int nt = 0; nt < NT; nt++)
#pragma unroll
            for (int r = 0; r < 4; r++) c[mt][nt][r] = 0.f;

    // loader indices: A 128x8 -> 4 elems/thread (float4); B 8xTN
    int la_row = tid >> 1, la_k = (tid & 1) * 4;
    int lb_k = tid >> 5;                                     // 0..7
    int lb_col = (TN == 128) ? ((tid & 31) * 4) : ((tid & 31) * 2);

    const float* Ag = A + (size_t)(bm + la_row) * K + la_k;
    const float* Bg = Bm + (size_t)lb_k * N + bn + lb_col;

    // preload chunk 0
    {
        float4 a4 = *(const float4*)(Ag);
        As2[0][la_k + 0][la_row] = tf32_split(a4.x);
        As2[0][la_k + 1][la_row] = tf32_split(a4.y);
        As2[0][la_k + 2][la_row] = tf32_split(a4.z);
        As2[0][la_k + 3][la_row] = tf32_split(a4.w);
        if (TN == 128) {
            float4 b4 = *(const float4*)(Bg);
            Bs2[0][lb_k][lb_col + 0] = tf32_split(b4.x);
            Bs2[0][lb_k][lb_col + 1] = tf32_split(b4.y);
            Bs2[0][lb_k][lb_col + 2] = tf32_split(b4.z);
            Bs2[0][lb_k][lb_col + 3] = tf32_split(b4.w);
        } else {
            float2 b2 = *(const float2*)(Bg);
            Bs2[0][lb_k][lb_col + 0] = tf32_split(b2.x);
            Bs2[0][lb_k][lb_col + 1] = tf32_split(b2.y);
        }
    }
    __syncthreads();

    int kcnt = K / 8;
    int buf = 0;
    for (int kc = 0; kc < kcnt; kc++) {
        bool more = (kc + 1) < kcnt;
        float4 pa, pb4;
        float2 pb2;
        if (more) {
            int ko = (kc + 1) * 8;
            pa = *(const float4*)(Ag + ko);
            if (TN == 128) pb4 = *(const float4*)(Bg + (size_t)ko * N);
            else           pb2 = *(const float2*)(Bg + (size_t)ko * N);
        }
        // ---- consume current buffer ----
        {
            uint2 bf[NT][2];
#pragma unroll
            for (int nt = 0; nt < NT; nt++) {
                int cb = warp_n * (TN / 4) + nt * 8 + g;
                bf[nt][0] = Bs2[buf][q][cb];
                bf[nt][1] = Bs2[buf][q + 4][cb];
            }
#pragma unroll
            for (int mt = 0; mt < 4; mt++) {
                int rb = warp_m * 64 + mt * 16 + g;
                uint2 af0 = As2[buf][q][rb];
                uint2 af1 = As2[buf][q][rb + 8];
                uint2 af2 = As2[buf][q + 4][rb];
                uint2 af3 = As2[buf][q + 4][rb + 8];
                uint32_t ah[4] = {af0.x, af1.x, af2.x, af3.x};
                uint32_t al[4] = {af0.y, af1.y, af2.y, af3.y};
#pragma unroll
                for (int nt = 0; nt < NT; nt++) {
                    uint32_t bh[2] = {bf[nt][0].x, bf[nt][1].x};
                    uint32_t bl[2] = {bf[nt][0].y, bf[nt][1].y};
                    mma_tf32(c[mt][nt], ah, bh);
                    mma_tf32(c[mt][nt], al, bh);
                    mma_tf32(c[mt][nt], ah, bl);
                }
            }
        }
        // ---- stage next buffer ----
        if (more) {
            int nb = buf ^ 1;
            As2[nb][la_k + 0][la_row] = tf32_split(pa.x);
            As2[nb][la_k + 1][la_row] = tf32_split(pa.y);
            As2[nb][la_k + 2][la_row] = tf32_split(pa.z);
            As2[nb][la_k + 3][la_row] = tf32_split(pa.w);
            if (TN == 128) {
                Bs2[nb][lb_k][lb_col + 0] = tf32_split(pb4.x);
                Bs2[nb][lb_k][lb_col + 1] = tf32_split(pb4.y);
                Bs2[nb][lb_k][lb_col + 2] = tf32_split(pb4.z);
                Bs2[nb][lb_k][lb_col + 3] = tf32_split(pb4.w);
            } else {
                Bs2[nb][lb_k][lb_col + 0] = tf32_split(pb2.x);
                Bs2[nb][lb_k][lb_col + 1] = tf32_split(pb2.y);
            }
            __syncthreads();
            buf = nb;
        }
    }

    // epilogue
#pragma unroll
    for (int mt = 0; mt < 4; mt++) {
        int row0 = bm + warp_m * 64 + mt * 16 + g;
        int row1 = row0 + 8;
#pragma unroll
        for (int nt = 0; nt < NT; nt++) {
            int col = bn + warp_n * (TN / 4) + nt * 8 + q * 2;
            float v00 = c[mt][nt][0] + bias[col];
            float v01 = c[mt][nt][1] + bias[col + 1];
            float v10 = c[mt][nt][2] + bias[col];
            float v11 = c[mt][nt][3] + bias[col + 1];
            if (epi == 1) {
                const float* r0 = res + (size_t)row0 * N + col;
                const float* r1 = res + (size_t)row1 * N + col;
                v00 += r0[0]; v01 += r0[1]; v10 += r1[0]; v11 += r1[1];
            } else if (epi == 2) {
                v00 = 0.5f * v00 * (1.f + erff(v00 * 0.70710678118654752f));
                v01 = 0.5f * v01 * (1.f + erff(v01 * 0.70710678118654752f));
                v10 = 0.5f * v10 * (1.f + erff(v10 * 0.70710678118654752f));
                v11 = 0.5f * v11 * (1.f + erff(v11 * 0.70710678118654752f));
            }
            *(float2*)(C + (size_t)row0 * N + col) = make_float2(v00, v01);
            *(float2*)(C + (size_t)row1 * N + col) = make_float2(v10, v11);
        }
    }
}

// ---------------- embedding projection (48 rows x 1536 cols, K=512) ---------
__global__ __launch_bounds__(256)
void emb_proj_kernel(const float* __restrict__ pe_emb, const float* __restrict__ ee_emb,
                     const float* __restrict__ W_in, const float* __restrict__ b_in,
                     float* __restrict__ pep, float* __restrict__ eep) {
    int m = blockIdx.y;
    int n = blockIdx.x * 256 + threadIdx.x;
    const float* emb = (m < 32) ? (pe_emb + (size_t)m * 512)
                                : (ee_emb + (size_t)(m - 32) * 512);
    __shared__ float se[512];
    for (int i = threadIdx.x; i < 512; i += 256) se[i] = emb[i];
    __syncthreads();
    float acc = b_in[n];
    const float* wp = W_in + n;
#pragma unroll 8
    for (int k = 0; k < 512; k++) acc = fmaf(se[k], wp[(size_t)k * 1536], acc);
    float* dst = (m < 32) ? (pep + (size_t)m * 1536) : (eep + (size_t)(m - 32) * 1536);
    dst[n] = acc;
}

// ---------------- bucket tables ---------------------------------------------
__global__ void bucket_tbl_kernel(float* __restrict__ out_pe, float* __restrict__ out_ee,
                                  const float* __restrict__ pep, const float* __restrict__ eep,
                                  const float* __restrict__ qkv, int proj_off, int kv_off) {
    int h = blockIdx.y, b = blockIdx.z;
    int j = blockIdx.x * 128 + threadIdx.x;
    __shared__ float sp[32][32];
    __shared__ float se[16][32];
    int tid = threadIdx.x;
    for (int idx = tid; idx < 32 * 32; idx += 128) {
        int p = idx >> 5, d = idx & 31;
        sp[p][d] = pep[(size_t)p * 1536 + proj_off + (h << 5) + d];
    }
    for (int idx = tid; idx < 16 * 32; idx += 128) {
        int p = idx >> 5, d = idx & 31;
        se[p][d] = eep[(size_t)p * 1536 + proj_off + (h << 5) + d];
    }
    __syncthreads();
    float kv[32];
    const float* src = qkv + (size_t)(j * Bsz + b) * 1536 + kv_off + (h << 5);
#pragma unroll
    for (int d = 0; d < 32; d += 4) {
        float4 t4 = *(const float4*)(src + d);
        kv[d] = t4.x; kv[d + 1] = t4.y; kv[d + 2] = t4.z; kv[d + 3] = t4.w;
    }
#pragma unroll 4
    for (int p = 0; p < 32; p++) {
        float s = 0.f;
#pragma unroll
        for (int d = 0; d < 32; d++) s += sp[p][d] * kv[d];
        out_pe[(size_t)((p * Bsz + b) * Hn + h) * Lq + j] = s;
    }
#pragma unroll 4
    for (int e = 0; e < 16; e++) {
        float s = 0.f;
#pragma unroll
        for (int d = 0; d < 32; d++) s += se[e][d] * kv[d];
        out_ee[(size_t)((e * Bsz + b) * Hn + h) * Lq + j] = s;
    }
}

// ---------------- attention scores + row-max partials ------------------------
__global__ __launch_bounds__(256)
void scores_kernel(const float* __restrict__ qkv, const float* __restrict__ edge,
                   const int* __restrict__ bdist, const int* __restrict__ etok,
                   const float* __restrict__ Ape, const float* __restrict__ Aee,
                   const float* __restrict__ Bpe, const float* __restrict__ Bee,
                   float* __restrict__ Sout, float* __restrict__ Mpart) {
    int bh = blockIdx.z;
    int b = bh >> 4, h = bh & 15;
    int i0 = blockIdx.y * 64, j0 = blockIdx.x * 64;
    __shared__ float Qs[32][64];
    __shared__ float Ks[32][64];
    __shared__ float redmx[64][16];
    int tid = threadIdx.x;
    int lr = tid >> 2, lc = (tid & 3) * 8;
    {
        const float* qsrc = qkv + (size_t)((i0 + lr) * Bsz + b) * 1536 + (h << 5) + lc;
        const float* ksrc = qkv + (size_t)((j0 + lr) * Bsz + b) * 1536 + 512 + (h << 5) + lc;
        float4 q0 = *(const float4*)qsrc;
        float4 q1 = *(const float4*)(qsrc + 4);
        float4 k0v = *(const float4*)ksrc;
        float4 k1v = *(const float4*)(ksrc + 4);
        Qs[lc + 0][lr] = q0.x; Qs[lc + 1][lr] = q0.y; Qs[lc + 2][lr] = q0.z; Qs[lc + 3][lr] = q0.w;
        Qs[lc + 4][lr] = q1.x; Qs[lc + 5][lr] = q1.y; Qs[lc + 6][lr] = q1.z; Qs[lc + 7][lr] = q1.w;
        Ks[lc + 0][lr] = k0v.x; Ks[lc + 1][lr] = k0v.y; Ks[lc + 2][lr] = k0v.z; Ks[lc + 3][lr] = k0v.w;
        Ks[lc + 4][lr] = k1v.x; Ks[lc + 5][lr] = k1v.y; Ks[lc + 6][lr] = k1v.z; Ks[lc + 7][lr] = k1v.w;
    }
    __syncthreads();
    float acc[4][4];
#pragma unroll
    for (int i = 0; i < 4; i++)
#pragma unroll
        for (int j = 0; j < 4; j++) acc[i][j] = 0.f;
    int ty = tid >> 4, tx = tid & 15;
#pragma unroll
    for (int k = 0; k < 32; k++) {
        float4 a = *(const float4*)&Qs[k][ty * 4];
        float4 bb = *(const float4*)&Ks[k][tx * 4];
        acc[0][0] += a.x * bb.x; acc[0][1] += a.x * bb.y; acc[0][2] += a.x * bb.z; acc[0][3] += a.x * bb.w;
        acc[1][0] += a.y * bb.x; acc[1][1] += a.y * bb.y; acc[1][2] += a.y * bb.z; acc[1][3] += a.y * bb.w;
        acc[2][0] += a.z * bb.x; acc[2][1] += a.z * bb.y; acc[2][2] += a.z * bb.z; acc[2][3] += a.z * bb.w;
        acc[3][0] += a.w * bb.x; acc[3][1] += a.w * bb.y; acc[3][2] += a.w * bb.z; acc[3][3] += a.w * bb.w;
    }
    const float inv_sqrt = 0.17677669529663687f;
    const float* eh = edge + (size_t)bh * LL;
    float* sh = Sout + (size_t)bh * LL;
    float rmax[4] = {-1e30f, -1e30f, -1e30f, -1e30f};
#pragma unroll
    for (int ii = 0; ii < 4; ii++) {
        int i = i0 + ty * 4 + ii;
#pragma unroll
        for (int jj = 0; jj < 4; jj++) {
            int j = j0 + tx * 4 + jj;
            int pidx = (i * Lq + j) * Bsz + b;
            int bd = bdist[pidx];
            int et = etok[pidx];
            float add = Ape[(size_t)((bd * Bsz + b) * Hn + h) * Lq + j]
                      + Aee[(size_t)((et * Bsz + b) * Hn + h) * Lq + j]
                      + Bpe[(size_t)((bd * Bsz + b) * Hn + h) * Lq + i]
                      + Bee[(size_t)((et * Bsz + b) * Hn + h) * Lq + i];
            float sval = (acc[ii][jj] + add) * inv_sqrt + eh[(size_t)i * Lq + j];
            sh[(size_t)i * Lq + j] = sval;
            rmax[ii] = fmaxf(rmax[ii], sval);
        }
        redmx[ty * 4 + ii][tx] = rmax[ii];
    }
    __syncthreads();
    if (tid < 64) {
        float m = redmx[tid][0];
#pragma unroll
        for (int t2 = 1; t2 < 16; t2++) m = fmaxf(m, redmx[tid][t2]);
        Mpart[(size_t)bh * 4096 + (size_t)(i0 + tid) * 8 + blockIdx.x] = m;
    }
}

// ---------------- fused softmax + PV ------------------------------------------
__global__ __launch_bounds__(256)
void softmax_pv_kernel(const float* __restrict__ S, const float* __restrict__ qkv,
                       const float* __restrict__ Mpart, float* __restrict__ ao) {
    int b = blockIdx.z, h = blockIdx.y;
    int bh = b * Hn + h;
    int i0 = blockIdx.x * 64;
    const float* Sh = S + (size_t)bh * LL;
    __shared__ float rowm[64], rowinv[64];
    __shared__ float lred[64][4];
    int tid = threadIdx.x;

    if (tid < 64) {
        const float* mp = Mpart + (size_t)bh * 4096 + (size_t)(i0 + tid) * 8;
        float m = mp[0];
#pragma unroll
        for (int t2 = 1; t2 < 8; t2++) m = fmaxf(m, mp[t2]);
        rowm[tid] = m;
    }
    __syncthreads();

    __shared__ float Ps[32][64];
    __shared__ float Vs[32][32];
    float acc[4][2] = {{0.f, 0.f}, {0.f, 0.f}, {0.f, 0.f}, {0.f, 0.f}};
    float lpart = 0.f;
    int rg = tid >> 4, cg = tid & 15;
    int lr = tid >> 2, lc = (tid & 3) * 8;
    int q = tid & 3;
    int vj = tid >> 3, vd = (tid & 7) * 4;

    for (int k0 = 0; k0 < Lq; k0 += 32) {
        float4 s0 = *(const float4*)(Sh + (size_t)(i0 + lr) * Lq + k0 + lc);
        float4 s1 = *(const float4*)(Sh + (size_t)(i0 + lr) * Lq + k0 + lc + 4);
        float4 v4 = *(const float4*)(qkv + (size_t)((k0 + vj) * Bsz + b) * 1536 + 1024 + (h << 5) + vd);
        float mval = rowm[lr];
        __syncthreads();
        float e0 = fast_exp(s0.x - mval);
        float e1 = fast_exp(s0.y - mval);
        float e2 = fast_exp(s0.z - mval);
        float e3 = fast_exp(s0.w - mval);
        float e4 = fast_exp(s1.x - mval);
        float e5 = fast_exp(s1.y - mval);
        float e6 = fast_exp(s1.z - mval);
        float e7 = fast_exp(s1.w - mval);
        Ps[lc + 0][lr] = e0; Ps[lc + 1][lr] = e1;
        Ps[lc + 2][lr] = e2; Ps[lc + 3][lr] = e3;
        Ps[lc + 4][lr] = e4; Ps[lc + 5][lr] = e5;
        Ps[lc + 6][lr] = e6; Ps[lc + 7][lr] = e7;
        lpart += ((e0 + e1) + (e2 + e3)) + ((e4 + e5) + (e6 + e7));
        *(float4*)&Vs[vj][vd] = v4;
        __syncthreads();
#pragma unroll
        for (int k = 0; k < 32; k++) {
            float4 a = *(const float4*)&Ps[k][rg * 4];
            float b0 = Vs[k][cg * 2], b1 = Vs[k][cg * 2 + 1];
            acc[0][0] += a.x * b0; acc[0][1] += a.x * b1;
            acc[1][0] += a.y * b0; acc[1][1] += a.y * b1;
            acc[2][0] += a.z * b0; acc[2][1] += a.z * b1;
            acc[3][0] += a.w * b0; acc[3][1] += a.w * b1;
        }
    }
    lred[lr][q] = lpart;
    __syncthreads();
    if (tid < 64)
        rowinv[tid] = 1.f / (((lred[tid][0] + lred[tid][1]) + (lred[tid][2] + lred[tid][3])));
    __syncthreads();
#pragma unroll
    for (int i = 0; i < 4; i++) {
        int rl = rg * 4 + i;
        float inv = rowinv[rl];
        int row = i0 + rl;
        float* dst = ao + (size_t)(row * Bsz + b) * 512 + (h << 5) + cg * 2;
        dst[0] = acc[i][0] * inv;
        dst[1] = acc[i][1] * inv;
    }
}

// ---------------- launch -----------------------------------------------------
extern "C" void kernel_launch(void* const* d_in, const int* in_sizes, int n_in,
                              void* d_out, int out_size) {
    const float* x      = (const float*)d_in[0];
    const float* edge   = (const float*)d_in[1];
    const int*   bdist  = (const int*)  d_in[2];
    const int*   etok   = (const int*)  d_in[3];
    const float* W_in   = (const float*)d_in[4];
    const float* b_in   = (const float*)d_in[5];
    const float* pe_emb = (const float*)d_in[6];
    const float* ee_emb = (const float*)d_in[7];
    const float* W_out  = (const float*)d_in[8];
    const float* b_out  = (const float*)d_in[9];
    const float* W1     = (const float*)d_in[10];
    const float* bb1    = (const float*)d_in[11];
    const float* W2     = (const float*)d_in[12];
    const float* bb2    = (const float*)d_in[13];
    const float* g1     = (const float*)d_in[14];
    const float* be1    = (const float*)d_in[15];
    const float* g2     = (const float*)d_in[16];
    const float* be2    = (const float*)d_in[17];

    float* out  = (float*)d_out;
    float* x2   = out;                     // [L,B,D]
    float* Sout = out + 2048 * 512;        // [B*H,L,L] — edge_out region

    float* scr = nullptr;
    cudaGetSymbolAddress((void**)&scr, g_scratch);
    float* hbuf  = scr + OFF_H;
    float* qkvb  = scr + OFF_QKV;
    float* pep   = scr + OFF_PEP;
    float* eep   = scr + OFF_EEP;
    float* Ape   = scr + OFF_APE;
    float* Aee   = scr + OFF_AEE;
    float* Bpe   = scr + OFF_BPE;
    float* Bee   = scr + OFF_BEE;
    float* aob   = scr + OFF_AO;
    float* x1b   = scr + OFF_X1;
    float* h2b   = scr + OFF_H2;
    float* ffb   = scr + OFF_FF;
    float* Mpart = scr + OFF_MP;

    // 1. LN1
    ln_kernel<<<2048, 128>>>(x, hbuf, g1, be1);
    // 2. QKV = h @ W_in + b_in  (tf32 split MMA)
    mma_gemm_kernel<128><<<dim3(1536 / 128, 2048 / 128), 256>>>(hbuf, W_in, b_in, nullptr, qkvb, 2048, 1536, 512, 0);
    // 3. projected embedding tables
    emb_proj_kernel<<<dim3(6, 48), 256>>>(pe_emb, ee_emb, W_in, b_in, pep, eep);
    // 4. bucket tables
    bucket_tbl_kernel<<<dim3(4, 16, 4), 128>>>(Ape, Aee, pep, eep, qkvb, 0, 512);
    bucket_tbl_kernel<<<dim3(4, 16, 4), 128>>>(Bpe, Bee, pep, eep, qkvb, 512, 0);
    // 5. scores S -> d_out edge region (+ row-max partials)
    scores_kernel<<<dim3(8, 8, 64), 256>>>(qkvb, edge, bdist, etok, Ape, Aee, Bpe, Bee, Sout, Mpart);
    // 6. fused softmax + PV -> ao
    softmax_pv_kernel<<<dim3(8, 16, 4), 256>>>(Sout, qkvb, Mpart, aob);
    // 7. x1 = x + ao @ W_out + b_out  (TN=64 -> 128 blocks)
    mma_gemm_kernel<64><<<dim3(512 / 64, 2048 / 128), 256>>>(aob, W_out, b_out, x, x1b, 2048, 512, 512, 1);
    // 8. LN2
    ln_kernel<<<2048, 128>>>(x1b, h2b, g2, be2);
    // 9. ff = gelu(h2 @ W1 + bb1)
    mma_gemm_kernel<128><<<dim3(2048 / 128, 2048 / 128), 256>>>(h2b, W1, bb1, nullptr, ffb, 2048, 2048, 512, 2);
    // 10. x2 = x1 + ff @ W2 + bb2
    mma_gemm_kernel<64><<<dim3(512 / 64, 2048 / 128), 256>>>(ffb, W2, bb2, x1b, x2, 2048, 512, 2048, 1);
}

// round 13
// speedup vs baseline: 1.3844x; 1.3844x over previous
#include <cuda_runtime.h>
#include <math.h>
#include <stdint.h>

// Problem constants
#define Lq     512
#define Bsz    4
#define Hn     16
#define LL     (512*512)

// ---------------- scratch (single static device buffer; no allocs) ----------
#define OFF_H    0u
#define OFF_QKV  (OFF_H    + 2048u*512u)          // 2048x1536
#define OFF_PEP  (OFF_QKV  + 2048u*1536u)         // 32x1536
#define OFF_EEP  (OFF_PEP  + 32u*1536u)           // 16x1536
#define OFF_APE  (OFF_EEP  + 16u*1536u)           // 32*4*16*512
#define OFF_AEE  (OFF_APE  + 32u*4u*16u*512u)
#define OFF_BPE  (OFF_AEE  + 16u*4u*16u*512u)
#define OFF_BEE  (OFF_BPE  + 32u*4u*16u*512u)
#define OFF_AO   (OFF_BEE  + 16u*4u*16u*512u)     // 2048x512
#define OFF_X1   (OFF_AO   + 2048u*512u)
#define OFF_H2   (OFF_X1   + 2048u*512u)
#define OFF_FF   (OFF_H2   + 2048u*512u)          // 2048x2048
#define OFF_MP   (OFF_FF   + 2048u*2048u)         // 64*512*8 row-max partials
#define SCRATCH_FLOATS (OFF_MP + 64u*512u*8u)

__device__ float g_scratch[SCRATCH_FLOATS];

// ---------------- helpers ----------------------------------------------------
__device__ __forceinline__ float fast_exp(float x) {
    float t = x * 1.4426950408889634f;
    t = fmaxf(t, -100.f);
    float r = rintf(t);
    float f = t - r;
    float p =            1.3333558146e-3f;
    p = fmaf(p, f, 9.6181291076e-3f);
    p = fmaf(p, f, 5.5504108664e-2f);
    p = fmaf(p, f, 2.4022650696e-1f);
    p = fmaf(p, f, 6.9314718056e-1f);
    p = fmaf(p, f, 1.0f);
    int e = (int)r;
    float sc = __int_as_float((e + 127) << 23);
    return p * sc;
}

__device__ __forceinline__ uint32_t f2tf32(float x) {
    uint32_t r;
    asm("cvt.rna.tf32.f32 %0, %1;" : "=r"(r) : "f"(x));
    return r;
}

__device__ __forceinline__ void mma_tf32(float* c, const uint32_t* a, const uint32_t* b) {
    asm volatile(
        "mma.sync.aligned.m16n8k8.row.col.f32.tf32.tf32.f32 "
        "{%0,%1,%2,%3}, {%4,%5,%6,%7}, {%8,%9}, {%0,%1,%2,%3};"
        : "+f"(c[0]), "+f"(c[1]), "+f"(c[2]), "+f"(c[3])
        : "r"(a[0]), "r"(a[1]), "r"(a[2]), "r"(a[3]), "r"(b[0]), "r"(b[1]));
}

// ---------------- LayerNorm ---------------------------------------------------
__global__ void ln_kernel(const float* __restrict__ in, float* __restrict__ out,
                          const float* __restrict__ gamma, const float* __restrict__ beta) {
    int row = blockIdx.x;
    const float* xr = in + (size_t)row * 512;
    int t = threadIdx.x;
    float v[4];
    float s = 0.f;
#pragma unroll
    for (int i = 0; i < 4; i++) { v[i] = xr[t + i * 128]; s += v[i]; }
    __shared__ float red[4];
#pragma unroll
    for (int o = 16; o; o >>= 1) s += __shfl_xor_sync(0xffffffffu, s, o);
    if ((t & 31) == 0) red[t >> 5] = s;
    __syncthreads();
    float mean = (red[0] + red[1] + red[2] + red[3]) * (1.f / 512.f);
    float vs = 0.f;
#pragma unroll
    for (int i = 0; i < 4; i++) { float d = v[i] - mean; vs += d * d; }
#pragma unroll
    for (int o = 16; o; o >>= 1) vs += __shfl_xor_sync(0xffffffffu, vs, o);
    __syncthreads();
    if ((t & 31) == 0) red[t >> 5] = vs;
    __syncthreads();
    float var = (red[0] + red[1] + red[2] + red[3]) * (1.f / 512.f);
    float rstd = rsqrtf(var + 1e-5f);
    float* orow = out + (size_t)row * 512;
#pragma unroll
    for (int i = 0; i < 4; i++) {
        int c = t + i * 128;
        orow[c] = (v[i] - mean) * rstd * gamma[c] + beta[c];
    }
}

// ---------------- tf32 2-term split MMA GEMM ----------------------------------
// C[M,N] = A[M,K] @ B[K,N] + bias  (+res | gelu). Tiles: 128 x TN, K-chunk 16.
// 256 threads = 8 warps in 2(M) x 4(N). Warp region: 64 x (TN/4).
// 2-term split: D += ahi*bhi + alo*bhi  (error ~2^-12, well under tolerance).
template<int TN>
__global__ __launch_bounds__(256)
void mma_gemm_kernel(const float* __restrict__ A, const float* __restrict__ Bm,
                     const float* __restrict__ bias, const float* __restrict__ res,
                     float* __restrict__ C, int M, int N, int K, int epi) {
    constexpr int NT = TN / 32;          // n-tiles per warp (4 or 2)
    constexpr int BSTR = TN + 8;         // B smem stride (conflict-free)
    __shared__ float As[2][128 * 20];    // [row][k], stride 20
    __shared__ float Bs[2][16 * BSTR];   // [k][col]

    int tid = threadIdx.x;
    int lane = tid & 31, wid = tid >> 5;
    int warp_m = wid >> 2, warp_n = wid & 3;
    int g = lane >> 2, q = lane & 3;
    int bm = blockIdx.y * 128, bn = blockIdx.x * TN;

    float c[4][NT][4];
#pragma unroll
    for (int mt = 0; mt < 4; mt++)
#pragma unroll
        for (int nt = 0; nt < NT; nt++)
#pragma unroll
            for (int r = 0; r < 4; r++) c[mt][nt][r] = 0.f;

    // loader indices
    int la_row = tid >> 2, la_col = (tid & 3) * 4;              // A: 2 rows per thread
    constexpr int BL = TN / 64;                                  // B float4 loads per thread
    int lb_k = (TN == 128) ? (tid >> 5) : (tid >> 4);
    int lb_col = (TN == 128) ? ((tid & 31) * 4) : ((tid & 15) * 4);

    const float* Ag0 = A + (size_t)(bm + la_row) * K + la_col;
    const float* Ag1 = A + (size_t)(bm + la_row + 64) * K + la_col;

    // preload chunk 0
    {
        float4 a0 = *(const float4*)(Ag0);
        float4 a1 = *(const float4*)(Ag1);
        *(float4*)&As[0][la_row * 20 + la_col] = a0;
        *(float4*)&As[0][(la_row + 64) * 20 + la_col] = a1;
#pragma unroll
        for (int l = 0; l < BL; l++) {
            int kk = lb_k + l * 8;
            float4 b4 = *(const float4*)(Bm + (size_t)kk * N + bn + lb_col);
            *(float4*)&Bs[0][kk * BSTR + lb_col] = b4;
        }
    }
    __syncthreads();

    int kcnt = K / 16;
    int buf = 0;
    for (int kc = 0; kc < kcnt; kc++) {
        bool more = (kc + 1) < kcnt;
        float4 pa0, pa1, pb[BL];
        if (more) {
            int ko = (kc + 1) * 16;
            pa0 = *(const float4*)(Ag0 + ko);
            pa1 = *(const float4*)(Ag1 + ko);
#pragma unroll
            for (int l = 0; l < BL; l++) {
                int kk = lb_k + l * 8;
                pb[l] = *(const float4*)(Bm + (size_t)(ko + kk) * N + bn + lb_col);
            }
        }
#pragma unroll
        for (int ks = 0; ks < 2; ks++) {
            int k0 = ks * 8;
            uint32_t ahi[4][4], alo[4][4], bhi[NT][2];
#pragma unroll
            for (int mt = 0; mt < 4; mt++) {
                int rb = warp_m * 64 + mt * 16 + g;
                const float* ap = &As[buf][rb * 20 + k0 + q];
                float x0 = ap[0], x1 = ap[160], x2 = ap[4], x3 = ap[164];
                ahi[mt][0] = f2tf32(x0); alo[mt][0] = f2tf32(x0 - __uint_as_float(ahi[mt][0]));
                ahi[mt][1] = f2tf32(x1); alo[mt][1] = f2tf32(x1 - __uint_as_float(ahi[mt][1]));
                ahi[mt][2] = f2tf32(x2); alo[mt][2] = f2tf32(x2 - __uint_as_float(ahi[mt][2]));
                ahi[mt][3] = f2tf32(x3); alo[mt][3] = f2tf32(x3 - __uint_as_float(ahi[mt][3]));
            }
#pragma unroll
            for (int nt = 0; nt < NT; nt++) {
                int cb = warp_n * (TN / 4) + nt * 8 + g;
                const float* bp = &Bs[buf][(k0 + q) * BSTR + cb];
                bhi[nt][0] = f2tf32(bp[0]);
                bhi[nt][1] = f2tf32(bp[4 * BSTR]);
            }
#pragma unroll
            for (int mt = 0; mt < 4; mt++)
#pragma unroll
                for (int nt = 0; nt < NT; nt++) {
                    mma_tf32(c[mt][nt], ahi[mt], bhi[nt]);
                    mma_tf32(c[mt][nt], alo[mt], bhi[nt]);
                }
        }
        if (more) {
            int nb = buf ^ 1;
            *(float4*)&As[nb][la_row * 20 + la_col] = pa0;
            *(float4*)&As[nb][(la_row + 64) * 20 + la_col] = pa1;
#pragma unroll
            for (int l = 0; l < BL; l++) {
                int kk = lb_k + l * 8;
                *(float4*)&Bs[nb][kk * BSTR + lb_col] = pb[l];
            }
            __syncthreads();
            buf = nb;
        }
    }

    // epilogue
#pragma unroll
    for (int mt = 0; mt < 4; mt++) {
        int row0 = bm + warp_m * 64 + mt * 16 + g;
        int row1 = row0 + 8;
#pragma unroll
        for (int nt = 0; nt < NT; nt++) {
            int col = bn + warp_n * (TN / 4) + nt * 8 + q * 2;
            float v00 = c[mt][nt][0] + bias[col];
            float v01 = c[mt][nt][1] + bias[col + 1];
            float v10 = c[mt][nt][2] + bias[col];
            float v11 = c[mt][nt][3] + bias[col + 1];
            if (epi == 1) {
                const float* r0 = res + (size_t)row0 * N + col;
                const float* r1 = res + (size_t)row1 * N + col;
                v00 += r0[0]; v01 += r0[1]; v10 += r1[0]; v11 += r1[1];
            } else if (epi == 2) {
                v00 = 0.5f * v00 * (1.f + erff(v00 * 0.70710678118654752f));
                v01 = 0.5f * v01 * (1.f + erff(v01 * 0.70710678118654752f));
                v10 = 0.5f * v10 * (1.f + erff(v10 * 0.70710678118654752f));
                v11 = 0.5f * v11 * (1.f + erff(v11 * 0.70710678118654752f));
            }
            *(float2*)(C + (size_t)row0 * N + col) = make_float2(v00, v01);
            *(float2*)(C + (size_t)row1 * N + col) = make_float2(v10, v11);
        }
    }
}

// ---------------- embedding projection (48 rows x 1536 cols, K=512) ---------
__global__ __launch_bounds__(256)
void emb_proj_kernel(const float* __restrict__ pe_emb, const float* __restrict__ ee_emb,
                     const float* __restrict__ W_in, const float* __restrict__ b_in,
                     float* __restrict__ pep, float* __restrict__ eep) {
    int m = blockIdx.y;
    int n = blockIdx.x * 256 + threadIdx.x;
    const float* emb = (m < 32) ? (pe_emb + (size_t)m * 512)
                                : (ee_emb + (size_t)(m - 32) * 512);
    __shared__ float se[512];
    for (int i = threadIdx.x; i < 512; i += 256) se[i] = emb[i];
    __syncthreads();
    float acc = b_in[n];
    const float* wp = W_in + n;
#pragma unroll 8
    for (int k = 0; k < 512; k++) acc = fmaf(se[k], wp[(size_t)k * 1536], acc);
    float* dst = (m < 32) ? (pep + (size_t)m * 1536) : (eep + (size_t)(m - 32) * 1536);
    dst[n] = acc;
}

// ---------------- bucket tables ---------------------------------------------
__global__ void bucket_tbl_kernel(float* __restrict__ out_pe, float* __restrict__ out_ee,
                                  const float* __restrict__ pep, const float* __restrict__ eep,
                                  const float* __restrict__ qkv, int proj_off, int kv_off) {
    int h = blockIdx.y, b = blockIdx.z;
    int j = blockIdx.x * 128 + threadIdx.x;
    __shared__ float sp[32][32];
    __shared__ float se[16][32];
    int tid = threadIdx.x;
    for (int idx = tid; idx < 32 * 32; idx += 128) {
        int p = idx >> 5, d = idx & 31;
        sp[p][d] = pep[(size_t)p * 1536 + proj_off + (h << 5) + d];
    }
    for (int idx = tid; idx < 16 * 32; idx += 128) {
        int p = idx >> 5, d = idx & 31;
        se[p][d] = eep[(size_t)p * 1536 + proj_off + (h << 5) + d];
    }
    __syncthreads();
    float kv[32];
    const float* src = qkv + (size_t)(j * Bsz + b) * 1536 + kv_off + (h << 5);
#pragma unroll
    for (int d = 0; d < 32; d += 4) {
        float4 t4 = *(const float4*)(src + d);
        kv[d] = t4.x; kv[d + 1] = t4.y; kv[d + 2] = t4.z; kv[d + 3] = t4.w;
    }
#pragma unroll 4
    for (int p = 0; p < 32; p++) {
        float s = 0.f;
#pragma unroll
        for (int d = 0; d < 32; d++) s += sp[p][d] * kv[d];
        out_pe[(size_t)((p * Bsz + b) * Hn + h) * Lq + j] = s;
    }
#pragma unroll 4
    for (int e = 0; e < 16; e++) {
        float s = 0.f;
#pragma unroll
        for (int d = 0; d < 32; d++) s += se[e][d] * kv[d];
        out_ee[(size_t)((e * Bsz + b) * Hn + h) * Lq + j] = s;
    }
}

// ---------------- attention scores + row-max partials ------------------------
__global__ __launch_bounds__(256)
void scores_kernel(const float* __restrict__ qkv, const float* __restrict__ edge,
                   const int* __restrict__ bdist, const int* __restrict__ etok,
                   const float* __restrict__ Ape, const float* __restrict__ Aee,
                   const float* __restrict__ Bpe, const float* __restrict__ Bee,
                   float* __restrict__ Sout, float* __restrict__ Mpart) {
    int bh = blockIdx.z;
    int b = bh >> 4, h = bh & 15;
    int i0 = blockIdx.y * 64, j0 = blockIdx.x * 64;
    __shared__ float Qs[32][64];
    __shared__ float Ks[32][64];
    __shared__ float redmx[64][16];
    int tid = threadIdx.x;
    int lr = tid >> 2, lc = (tid & 3) * 8;
    {
        const float* qsrc = qkv + (size_t)((i0 + lr) * Bsz + b) * 1536 + (h << 5) + lc;
        const float* ksrc = qkv + (size_t)((j0 + lr) * Bsz + b) * 1536 + 512 + (h << 5) + lc;
        float4 q0 = *(const float4*)qsrc;
        float4 q1 = *(const float4*)(qsrc + 4);
        float4 k0v = *(const float4*)ksrc;
        float4 k1v = *(const float4*)(ksrc + 4);
        Qs[lc + 0][lr] = q0.x; Qs[lc + 1][lr] = q0.y; Qs[lc + 2][lr] = q0.z; Qs[lc + 3][lr] = q0.w;
        Qs[lc + 4][lr] = q1.x; Qs[lc + 5][lr] = q1.y; Qs[lc + 6][lr] = q1.z; Qs[lc + 7][lr] = q1.w;
        Ks[lc + 0][lr] = k0v.x; Ks[lc + 1][lr] = k0v.y; Ks[lc + 2][lr] = k0v.z; Ks[lc + 3][lr] = k0v.w;
        Ks[lc + 4][lr] = k1v.x; Ks[lc + 5][lr] = k1v.y; Ks[lc + 6][lr] = k1v.z; Ks[lc + 7][lr] = k1v.w;
    }
    __syncthreads();
    float acc[4][4];
#pragma unroll
    for (int i = 0; i < 4; i++)
#pragma unroll
        for (int j = 0; j < 4; j++) acc[i][j] = 0.f;
    int ty = tid >> 4, tx = tid & 15;
#pragma unroll
    for (int k = 0; k < 32; k++) {
        float4 a = *(const float4*)&Qs[k][ty * 4];
        float4 bb = *(const float4*)&Ks[k][tx * 4];
        acc[0][0] += a.x * bb.x; acc[0][1] += a.x * bb.y; acc[0][2] += a.x * bb.z; acc[0][3] += a.x * bb.w;
        acc[1][0] += a.y * bb.x; acc[1][1] += a.y * bb.y; acc[1][2] += a.y * bb.z; acc[1][3] += a.y * bb.w;
        acc[2][0] += a.z * bb.x; acc[2][1] += a.z * bb.y; acc[2][2] += a.z * bb.z; acc[2][3] += a.z * bb.w;
        acc[3][0] += a.w * bb.x; acc[3][1] += a.w * bb.y; acc[3][2] += a.w * bb.z; acc[3][3] += a.w * bb.w;
    }
    const float inv_sqrt = 0.17677669529663687f;
    const float* eh = edge + (size_t)bh * LL;
    float* sh = Sout + (size_t)bh * LL;
    float rmax[4] = {-1e30f, -1e30f, -1e30f, -1e30f};
#pragma unroll
    for (int ii = 0; ii < 4; ii++) {
        int i = i0 + ty * 4 + ii;
#pragma unroll
        for (int jj = 0; jj < 4; jj++) {
            int j = j0 + tx * 4 + jj;
            int pidx = (i * Lq + j) * Bsz + b;
            int bd = bdist[pidx];
            int et = etok[pidx];
            float add = Ape[(size_t)((bd * Bsz + b) * Hn + h) * Lq + j]
                      + Aee[(size_t)((et * Bsz + b) * Hn + h) * Lq + j]
                      + Bpe[(size_t)((bd * Bsz + b) * Hn + h) * Lq + i]
                      + Bee[(size_t)((et * Bsz + b) * Hn + h) * Lq + i];
            float sval = (acc[ii][jj] + add) * inv_sqrt + eh[(size_t)i * Lq + j];
            sh[(size_t)i * Lq + j] = sval;
            rmax[ii] = fmaxf(rmax[ii], sval);
        }
        redmx[ty * 4 + ii][tx] = rmax[ii];
    }
    __syncthreads();
    if (tid < 64) {
        float m = redmx[tid][0];
#pragma unroll
        for (int t2 = 1; t2 < 16; t2++) m = fmaxf(m, redmx[tid][t2]);
        Mpart[(size_t)bh * 4096 + (size_t)(i0 + tid) * 8 + blockIdx.x] = m;
    }
}

// ---------------- fused softmax + PV ------------------------------------------
__global__ __launch_bounds__(256)
void softmax_pv_kernel(const float* __restrict__ S, const float* __restrict__ qkv,
                       const float* __restrict__ Mpart, float* __restrict__ ao) {
    int b = blockIdx.z, h = blockIdx.y;
    int bh = b * Hn + h;
    int i0 = blockIdx.x * 64;
    const float* Sh = S + (size_t)bh * LL;
    __shared__ float rowm[64], rowinv[64];
    __shared__ float lred[64][4];
    int tid = threadIdx.x;

    if (tid < 64) {
        const float* mp = Mpart + (size_t)bh * 4096 + (size_t)(i0 + tid) * 8;
        float m = mp[0];
#pragma unroll
        for (int t2 = 1; t2 < 8; t2++) m = fmaxf(m, mp[t2]);
        rowm[tid] = m;
    }
    __syncthreads();

    __shared__ float Ps[32][64];
    __shared__ float Vs[32][32];
    float acc[4][2] = {{0.f, 0.f}, {0.f, 0.f}, {0.f, 0.f}, {0.f, 0.f}};
    float lpart = 0.f;
    int rg = tid >> 4, cg = tid & 15;
    int lr = tid >> 2, lc = (tid & 3) * 8;
    int q = tid & 3;
    int vj = tid >> 3, vd = (tid & 7) * 4;

    for (int k0 = 0; k0 < Lq; k0 += 32) {
        float4 s0 = *(const float4*)(Sh + (size_t)(i0 + lr) * Lq + k0 + lc);
        float4 s1 = *(const float4*)(Sh + (size_t)(i0 + lr) * Lq + k0 + lc + 4);
        float4 v4 = *(const float4*)(qkv + (size_t)((k0 + vj) * Bsz + b) * 1536 + 1024 + (h << 5) + vd);
        float mval = rowm[lr];
        __syncthreads();
        float e0 = fast_exp(s0.x - mval);
        float e1 = fast_exp(s0.y - mval);
        float e2 = fast_exp(s0.z - mval);
        float e3 = fast_exp(s0.w - mval);
        float e4 = fast_exp(s1.x - mval);
        float e5 = fast_exp(s1.y - mval);
        float e6 = fast_exp(s1.z - mval);
        float e7 = fast_exp(s1.w - mval);
        Ps[lc + 0][lr] = e0; Ps[lc + 1][lr] = e1;
        Ps[lc + 2][lr] = e2; Ps[lc + 3][lr] = e3;
        Ps[lc + 4][lr] = e4; Ps[lc + 5][lr] = e5;
        Ps[lc + 6][lr] = e6; Ps[lc + 7][lr] = e7;
        lpart += ((e0 + e1) + (e2 + e3)) + ((e4 + e5) + (e6 + e7));
        *(float4*)&Vs[vj][vd] = v4;
        __syncthreads();
#pragma unroll
        for (int k = 0; k < 32; k++) {
            float4 a = *(const float4*)&Ps[k][rg * 4];
            float b0 = Vs[k][cg * 2], b1 = Vs[k][cg * 2 + 1];
            acc[0][0] += a.x * b0; acc[0][1] += a.x * b1;
            acc[1][0] += a.y * b0; acc[1][1] += a.y * b1;
            acc[2][0] += a.z * b0; acc[2][1] += a.z * b1;
            acc[3][0] += a.w * b0; acc[3][1] += a.w * b1;
        }
    }
    lred[lr][q] = lpart;
    __syncthreads();
    if (tid < 64)
        rowinv[tid] = 1.f / (((lred[tid][0] + lred[tid][1]) + (lred[tid][2] + lred[tid][3])));
    __syncthreads();
#pragma unroll
    for (int i = 0; i < 4; i++) {
        int rl = rg * 4 + i;
        float inv = rowinv[rl];
        int row = i0 + rl;
        float* dst = ao + (size_t)(row * Bsz + b) * 512 + (h << 5) + cg * 2;
        dst[0] = acc[i][0] * inv;
        dst[1] = acc[i][1] * inv;
    }
}

// ---------------- launch -----------------------------------------------------
extern "C" void kernel_launch(void* const* d_in, const int* in_sizes, int n_in,
                              void* d_out, int out_size) {
    const float* x      = (const float*)d_in[0];
    const float* edge   = (const float*)d_in[1];
    const int*   bdist  = (const int*)  d_in[2];
    const int*   etok   = (const int*)  d_in[3];
    const float* W_in   = (const float*)d_in[4];
    const float* b_in   = (const float*)d_in[5];
    const float* pe_emb = (const float*)d_in[6];
    const float* ee_emb = (const float*)d_in[7];
    const float* W_out  = (const float*)d_in[8];
    const float* b_out  = (const float*)d_in[9];
    const float* W1     = (const float*)d_in[10];
    const float* bb1    = (const float*)d_in[11];
    const float* W2     = (const float*)d_in[12];
    const float* bb2    = (const float*)d_in[13];
    const float* g1     = (const float*)d_in[14];
    const float* be1    = (const float*)d_in[15];
    const float* g2     = (const float*)d_in[16];
    const float* be2    = (const float*)d_in[17];

    float* out  = (float*)d_out;
    float* x2   = out;                     // [L,B,D]
    float* Sout = out + 2048 * 512;        // [B*H,L,L] — edge_out region

    float* scr = nullptr;
    cudaGetSymbolAddress((void**)&scr, g_scratch);
    float* hbuf  = scr + OFF_H;
    float* qkvb  = scr + OFF_QKV;
    float* pep   = scr + OFF_PEP;
    float* eep   = scr + OFF_EEP;
    float* Ape   = scr + OFF_APE;
    float* Aee   = scr + OFF_AEE;
    float* Bpe   = scr + OFF_BPE;
    float* Bee   = scr + OFF_BEE;
    float* aob   = scr + OFF_AO;
    float* x1b   = scr + OFF_X1;
    float* h2b   = scr + OFF_H2;
    float* ffb   = scr + OFF_FF;
    float* Mpart = scr + OFF_MP;

    // 1. LN1
    ln_kernel<<<2048, 128>>>(x, hbuf, g1, be1);
    // 2. QKV = h @ W_in + b_in  (tf32 2-term MMA)
    mma_gemm_kernel<128><<<dim3(1536 / 128, 2048 / 128), 256>>>(hbuf, W_in, b_in, nullptr, qkvb, 2048, 1536, 512, 0);
    // 3. projected embedding tables
    emb_proj_kernel<<<dim3(6, 48), 256>>>(pe_emb, ee_emb, W_in, b_in, pep, eep);
    // 4. bucket tables
    bucket_tbl_kernel<<<dim3(4, 16, 4), 128>>>(Ape, Aee, pep, eep, qkvb, 0, 512);
    bucket_tbl_kernel<<<dim3(4, 16, 4), 128>>>(Bpe, Bee, pep, eep, qkvb, 512, 0);
    // 5. scores S -> d_out edge region (+ row-max partials)
    scores_kernel<<<dim3(8, 8, 64), 256>>>(qkvb, edge, bdist, etok, Ape, Aee, Bpe, Bee, Sout, Mpart);
    // 6. fused softmax + PV -> ao
    softmax_pv_kernel<<<dim3(8, 16, 4), 256>>>(Sout, qkvb, Mpart, aob);
    // 7. x1 = x + ao @ W_out + b_out  (TN=64 -> 128 blocks)
    mma_gemm_kernel<64><<<dim3(512 / 64, 2048 / 128), 256>>>(aob, W_out, b_out, x, x1b, 2048, 512, 512, 1);
    // 8. LN2
    ln_kernel<<<2048, 128>>>(x1b, h2b, g2, be2);
    // 9. ff = gelu(h2 @ W1 + bb1)
    mma_gemm_kernel<128><<<dim3(2048 / 128, 2048 / 128), 256>>>(h2b, W1, bb1, nullptr, ffb, 2048, 2048, 512, 2);
    // 10. x2 = x1 + ff @ W2 + bb2
    mma_gemm_kernel<64><<<dim3(512 / 64, 2048 / 128), 256>>>(ffb, W2, bb2, x1b, x2, 2048, 512, 2048, 1);
}